// round 16
// baseline (speedup 1.0000x reference)
#include <cuda_runtime.h>
#include <cstdint>
#include <math.h>

#define BB 8
#define CC 512
#define LL 2048

// ---------------- global scratch (no allocation) ----------------
__device__ float g_wr[3 * CC * CC];            // tf32-rounded W (q,k,v concat)
__device__ float g_xr[BB * CC * LL];           // tf32-rounded x
__device__ float g_q[BB * CC * LL];            // tf32-rounded q  [b][c][l]
__device__ float g_k[BB * CC * LL];            // tf32-rounded k  [b][c][l]
__device__ float g_v[BB * CC * LL];            // tf32-rounded v  [b][c][l]
__device__ float g_s[(size_t)BB * LL * LL];    // E = exp(scores)  [b][l][m]
__device__ float g_part[BB * LL * 16];         // per-tile row partial sums
__device__ float g_inv[BB * LL];               // 1 / row sum

__device__ __forceinline__ float tf32r(float f) {
    unsigned u;
    asm("cvt.rna.tf32.f32 %0, %1;" : "=r"(u) : "f"(f));
    return __uint_as_float(u);
}

__device__ __forceinline__ uint32_t smem_u32(const void* p) {
    uint32_t a;
    asm("{ .reg .u64 t; cvta.to.shared.u64 t, %1; cvt.u32.u64 %0, t; }" : "=r"(a) : "l"(p));
    return a;
}

__device__ __forceinline__ void mma_tf32(float* d, const float* a, const float* b) {
    asm volatile(
        "mma.sync.aligned.m16n8k8.row.col.f32.tf32.tf32.f32 "
        "{%0,%1,%2,%3}, {%4,%5,%6,%7}, {%8,%9}, {%0,%1,%2,%3};"
        : "+f"(d[0]), "+f"(d[1]), "+f"(d[2]), "+f"(d[3])
        : "r"(__float_as_uint(a[0])), "r"(__float_as_uint(a[1])),
          "r"(__float_as_uint(a[2])), "r"(__float_as_uint(a[3])),
          "r"(__float_as_uint(b[0])), "r"(__float_as_uint(b[1])));
}

#define CP16(d, s)  asm volatile("cp.async.cg.shared.global [%0], [%1], 16;" :: "r"(d), "l"(s))
#define CPCOMMIT()  asm volatile("cp.async.commit_group;" ::: "memory")
#define CPWAIT2()   asm volatile("cp.async.wait_group 2;" ::: "memory")

// ---------------------------------------------------------------------------
// tf32 mma.sync GEMM. 4-stage cp.async pipeline, native-orientation smem.
//   ALAY: 0 = A is MxK row-major (stride-20 rows), 1 = A is KxM (stride-136)
//   BLAY: 0 = B is KxN (stride-136),               1 = B is NxK (stride-20)
// EPI: 0 = qkv   (tf32r(acc*scale + bias[m]), aux = bias)
//      1 = exp   (E = tf32r(exp(acc*scale)) + deterministic row partials,
//                 aux = g_part batch base)
//      2 = inv   (acc * aux[n], aux = g_inv batch base)
// Block 128x128, 128 threads = 4 warps (2M x 2N), warp tile 64x64, BK=16.
// ---------------------------------------------------------------------------
constexpr int BM = 128, BN = 128, BK = 16, STAGES = 4;

template <int ALAY, int BLAY, int EPI>
__device__ __forceinline__ void gemm_body(
    const float* __restrict__ A, const float* __restrict__ B,
    float* __restrict__ C, int K,
    int lda, int ldb, int ldc,
    float scale, const float* __restrict__ aux, float* __restrict__ aux_out)
{
    extern __shared__ float sm[];
    constexpr int AW = (ALAY == 1) ? 136 : 20;
    constexpr int AR = (ALAY == 1) ? 16 : 128;
    constexpr int BW = (BLAY == 1) ? 20 : 136;
    constexpr int BR = (BLAY == 1) ? 128 : 16;
    constexpr int ASZ = AR * AW, BSZ = BR * BW;

    float* Ab = sm;
    float* Bb = sm + STAGES * ASZ;
    const uint32_t abase = smem_u32(Ab);
    const uint32_t bbase = smem_u32(Bb);

    const int tid  = threadIdx.x;        // 0..127
    const int lane = tid & 31;
    const int warp = tid >> 5;           // 0..3
    const int wm = warp & 1;             // M dir (64 rows)
    const int wn = warp >> 1;            // N dir (64 cols)
    const int r = lane >> 2;             // 0..7
    const int c = lane & 3;              // 0..3
    const int m0 = blockIdx.y * BM;
    const int n0 = blockIdx.x * BN;

    float acc[4][8][4];
#pragma unroll
    for (int i = 0; i < 4; i++)
#pragma unroll
        for (int j = 0; j < 8; j++)
#pragma unroll
            for (int q = 0; q < 4; q++) acc[i][j][q] = 0.0f;

    auto issue = [&](int slot, int k0) {
#pragma unroll
        for (int it = 0; it < 4; it++) {
            const int i = tid + 128 * it;            // 0..511
            if (ALAY == 0) {
                const int row = i >> 2, c4 = i & 3;
                CP16(abase + 4 * (slot * ASZ + row * 20 + 4 * c4),
                     A + (size_t)(m0 + row) * lda + k0 + 4 * c4);
            } else {
                const int row = i >> 5, cc = i & 31;
                CP16(abase + 4 * (slot * ASZ + row * 136 + 4 * cc),
                     A + (size_t)(k0 + row) * lda + m0 + 4 * cc);
            }
            if (BLAY == 0) {
                const int row = i >> 5, cc = i & 31;
                CP16(bbase + 4 * (slot * BSZ + row * 136 + 4 * cc),
                     B + (size_t)(k0 + row) * ldb + n0 + 4 * cc);
            } else {
                const int row = i >> 2, c4 = i & 3;
                CP16(bbase + 4 * (slot * BSZ + row * 20 + 4 * c4),
                     B + (size_t)(n0 + row) * ldb + k0 + 4 * c4);
            }
        }
    };

    auto compute = [&](int slot) {
        const float* Asl = Ab + slot * ASZ;
        const float* Bsl = Bb + slot * BSZ;
#pragma unroll
        for (int ks = 0; ks < 2; ks++) {
            const int kb = ks * 8;
            float af[4][4], bf[8][2];
#pragma unroll
            for (int i = 0; i < 4; i++) {
                const int mb = wm * 64 + i * 16;
                if (ALAY == 1) {
                    af[i][0] = Asl[(kb + c) * 136 + mb + r];
                    af[i][1] = Asl[(kb + c) * 136 + mb + r + 8];
                    af[i][2] = Asl[(kb + c + 4) * 136 + mb + r];
                    af[i][3] = Asl[(kb + c + 4) * 136 + mb + r + 8];
                } else {
                    af[i][0] = Asl[(mb + r) * 20 + kb + c];
                    af[i][1] = Asl[(mb + r + 8) * 20 + kb + c];
                    af[i][2] = Asl[(mb + r) * 20 + kb + c + 4];
                    af[i][3] = Asl[(mb + r + 8) * 20 + kb + c + 4];
                }
            }
#pragma unroll
            for (int j = 0; j < 8; j++) {
                const int nb = wn * 64 + j * 8;
                if (BLAY == 0) {
                    bf[j][0] = Bsl[(kb + c) * 136 + nb + r];
                    bf[j][1] = Bsl[(kb + c + 4) * 136 + nb + r];
                } else {
                    bf[j][0] = Bsl[(nb + r) * 20 + kb + c];
                    bf[j][1] = Bsl[(nb + r) * 20 + kb + c + 4];
                }
            }
#pragma unroll
            for (int i = 0; i < 4; i++)
#pragma unroll
                for (int j = 0; j < 8; j++)
                    mma_tf32(acc[i][j], af[i], bf[j]);
        }
    };

    // prologue: prefetch 3 stages
    issue(0, 0);       CPCOMMIT();
    issue(1, BK);      CPCOMMIT();
    issue(2, 2 * BK);  CPCOMMIT();

    const int NT = K / BK;
    for (int t = 0; t < NT; t++) {
        CPWAIT2();                 // stage t complete
        __syncthreads();
        const int nxt = t + 3;
        if (nxt < NT) issue(nxt & 3, nxt * BK);   // overlap loads w/ compute
        CPCOMMIT();
        compute(t & 3);
    }

    // ---- epilogues ----
    if (EPI == 0) {
#pragma unroll
        for (int i = 0; i < 4; i++) {
            const int m = m0 + wm * 64 + i * 16 + r;
            const float bv0 = __ldg(&aux[m]);
            const float bv1 = __ldg(&aux[m + 8]);
#pragma unroll
            for (int j = 0; j < 8; j++) {
                const int n = n0 + wn * 64 + j * 8 + 2 * c;
                *(float2*)&C[(size_t)m * ldc + n] =
                    make_float2(tf32r(acc[i][j][0] * scale + bv0),
                                tf32r(acc[i][j][1] * scale + bv0));
                *(float2*)&C[(size_t)(m + 8) * ldc + n] =
                    make_float2(tf32r(acc[i][j][2] * scale + bv1),
                                tf32r(acc[i][j][3] * scale + bv1));
            }
        }
    } else if (EPI == 1) {
        __shared__ float sred[128][9];
#pragma unroll
        for (int i = 0; i < 4; i++) {
            const int row0 = wm * 64 + i * 16 + r;
            const int m = m0 + row0;
            float s0 = 0.0f, s1 = 0.0f;
#pragma unroll
            for (int j = 0; j < 8; j++) {
                const int n = n0 + wn * 64 + j * 8 + 2 * c;
                const float e0 = tf32r(__expf(acc[i][j][0] * scale));
                const float e1 = tf32r(__expf(acc[i][j][1] * scale));
                const float e2 = tf32r(__expf(acc[i][j][2] * scale));
                const float e3 = tf32r(__expf(acc[i][j][3] * scale));
                *(float2*)&C[(size_t)m * ldc + n]       = make_float2(e0, e1);
                *(float2*)&C[(size_t)(m + 8) * ldc + n] = make_float2(e2, e3);
                s0 += e0 + e1;
                s1 += e2 + e3;
            }
            sred[row0][wn * 4 + c]     = s0;
            sred[row0 + 8][wn * 4 + c] = s1;
        }
        __syncthreads();
        // fixed-order combine: thread t sums row t's 8 slots -> deterministic
        {
            float s = 0.0f;
#pragma unroll
            for (int u = 0; u < 8; u++) s += sred[tid][u];
            aux_out[(size_t)(m0 + tid) * 16 + blockIdx.x] = s;
        }
    } else {  // EPI == 2
#pragma unroll
        for (int i = 0; i < 4; i++) {
            const int m = m0 + wm * 64 + i * 16 + r;
#pragma unroll
            for (int j = 0; j < 8; j++) {
                const int n = n0 + wn * 64 + j * 8 + 2 * c;
                const float2 iv = *(const float2*)&aux[n];
                *(float2*)&C[(size_t)m * ldc + n] =
                    make_float2(acc[i][j][0] * iv.x, acc[i][j][1] * iv.y);
                *(float2*)&C[(size_t)(m + 8) * ldc + n] =
                    make_float2(acc[i][j][2] * iv.x, acc[i][j][3] * iv.y);
            }
        }
    }
}

// smem sizes (bytes) per instantiation (4 stages, dynamic part)
constexpr int SMEM_QKV = STAGES * (128 * 20 + 16 * 136) * 4;   // 75776
constexpr int SMEM_SCO = STAGES * (16 * 136 + 16 * 136) * 4;   // 69632
constexpr int SMEM_OUT = STAGES * (128 * 20 + 128 * 20) * 4;   // 81920

// ---------------------------------------------------------------------------
// prep: tf32-round W and x elementwise
// ---------------------------------------------------------------------------
__global__ __launch_bounds__(256) void prep_w(
    const float* __restrict__ Wq, const float* __restrict__ Wk,
    const float* __restrict__ Wv)
{
    const int i = blockIdx.x * 256 + threadIdx.x;       // 786432
    const int p = i >> 18, rr = i & 0x3FFFF;
    g_wr[i] = tf32r((p == 0 ? Wq : p == 1 ? Wk : Wv)[rr]);
}

__global__ __launch_bounds__(256) void prep_x(const float* __restrict__ x)
{
    const size_t i = (size_t)blockIdx.x * 1024 + threadIdx.x * 4;
    float4 f = *(const float4*)&x[i];
    f.x = tf32r(f.x); f.y = tf32r(f.y); f.z = tf32r(f.z); f.w = tf32r(f.w);
    *(float4*)&g_xr[i] = f;
}

// ---------------------------------------------------------------------------
// GEMM kernels (128 threads, 2 CTAs/SM)
// ---------------------------------------------------------------------------
__global__ __launch_bounds__(128, 2) void qkv_kernel(
    const float* __restrict__ bq, const float* __restrict__ bk,
    const float* __restrict__ bv)
{
    const int z = blockIdx.z;
    const int p = z >> 3;
    const int b = z & 7;
    const float* W  = g_wr + (size_t)p * CC * CC;
    const float* bi = (p == 0) ? bq : (p == 1) ? bk : bv;
    float* out = ((p == 0) ? g_q : (p == 1) ? g_k : g_v) + (size_t)b * CC * LL;
    const float* xb = g_xr + (size_t)b * CC * LL;
    gemm_body<0, 0, 0>(W, xb, out, CC, CC, LL, LL, 1.0f, bi, nullptr);
}

// scores + exp fused: writes E = exp(q.k/sqrt(C)) and per-tile row sums
__global__ __launch_bounds__(128, 2) void scores_kernel()
{
    const int b = blockIdx.z;
    const float* Q  = g_q + (size_t)b * CC * LL;
    const float* Kp = g_k + (size_t)b * CC * LL;
    float* S = g_s + (size_t)b * LL * LL;
    float* part = g_part + (size_t)b * LL * 16;
    gemm_body<1, 0, 1>(Q, Kp, S, CC, LL, LL, LL,
                       0.044194173824159216f, nullptr, part);
}

// row sums -> reciprocal (deterministic fixed-order)
__global__ __launch_bounds__(256) void sumrow_kernel()
{
    const int i = blockIdx.x * 256 + threadIdx.x;   // 16384 rows
    const float* p = g_part + (size_t)i * 16;
    float s = 0.0f;
#pragma unroll
    for (int u = 0; u < 16; u++) s += p[u];
    g_inv[i] = 1.0f / s;
}

// out = (V @ E^T) * inv[l]
__global__ __launch_bounds__(128, 2) void out_kernel(float* __restrict__ out)
{
    const int b = blockIdx.z;
    const float* V = g_v + (size_t)b * CC * LL;
    const float* E = g_s + (size_t)b * LL * LL;
    const float* iv = g_inv + (size_t)b * LL;
    float* O = out + (size_t)b * CC * LL;
    gemm_body<0, 1, 2>(V, E, O, LL, LL, LL, LL, 1.0f, iv, nullptr);
}

// ---------------------------------------------------------------------------
extern "C" void kernel_launch(void* const* d_in, const int* in_sizes, int n_in,
                              void* d_out, int out_size)
{
    const float* x  = (const float*)d_in[0];
    const float* Wq = (const float*)d_in[1];
    const float* bq = (const float*)d_in[2];
    const float* Wk = (const float*)d_in[3];
    const float* bk = (const float*)d_in[4];
    const float* Wv = (const float*)d_in[5];
    const float* bv = (const float*)d_in[6];
    float* out = (float*)d_out;

    cudaFuncSetAttribute(qkv_kernel,    cudaFuncAttributeMaxDynamicSharedMemorySize, SMEM_QKV);
    cudaFuncSetAttribute(scores_kernel, cudaFuncAttributeMaxDynamicSharedMemorySize, SMEM_SCO);
    cudaFuncSetAttribute(out_kernel,    cudaFuncAttributeMaxDynamicSharedMemorySize, SMEM_OUT);

    dim3 blk(128);

    prep_w<<<3 * CC * CC / 256, 256>>>(Wq, Wk, Wv);
    prep_x<<<BB * CC * LL / 1024, 256>>>(x);

    dim3 g1(LL / BN, CC / BM, 3 * BB);
    qkv_kernel<<<g1, blk, SMEM_QKV>>>(bq, bk, bv);

    dim3 g2(LL / BN, LL / BM, BB);
    scores_kernel<<<g2, blk, SMEM_SCO>>>();

    sumrow_kernel<<<BB * LL / 256, 256>>>();

    dim3 g4(LL / BN, CC / BM, BB);
    out_kernel<<<g4, blk, SMEM_OUT>>>(out);
}